// round 7
// baseline (speedup 1.0000x reference)
#include <cuda_runtime.h>
#include <cuda_bf16.h>
#include <mma.h>
#include <math.h>
#include <stdint.h>

#define NN      4096
#define NFEAT   512
#define NHID    64
#define NHEADS  8
#define NCLASS  41
#define HD      (NHEADS*NHID)   /* 512 */
#define MAXD    256
#define ALPHA   0.2f
#define KSPLIT  8

using namespace nvcuda;

/* scratch */
__device__ int            g_deg[NN];
__device__ int            g_nbr[NN*MAXD];
__device__ float          g_Wh [NN*HD];
__device__ float          g_s1 [NHEADS*NN];
__device__ float          g_s2 [NHEADS*NN];
__device__ float          g_h  [NN*HD];
__device__ float          g_Wh2[NN*NCLASS];
__device__ float          g_p1 [NN];
__device__ float          g_p2 [NN];
__device__ float          g_part[KSPLIT*NN*48];
__device__ __nv_bfloat16  g_xhi[NN*NFEAT];
__device__ __nv_bfloat16  g_xlo[NN*NFEAT];
__device__ __nv_bfloat16  g_wthi[NFEAT*HD];   /* [f][h*64+d] */
__device__ __nv_bfloat16  g_wtlo[NFEAT*HD];

/* ------------------------------------------------------------------ */
/* convert: x -> bf16 hi/lo ; W_heads -> transposed bf16 hi/lo         */
__global__ void convert(const float* __restrict__ x, const float* __restrict__ Wv) {
    const int id = blockIdx.x * blockDim.x + threadIdx.x;
    const int stride = gridDim.x * blockDim.x;
    for (int i = id; i < NN * NFEAT / 4; i += stride) {
        float4 v = ((const float4*)x)[i];
        __nv_bfloat162 h0, h1, l0, l1;
        h0.x = __float2bfloat16(v.x); h0.y = __float2bfloat16(v.y);
        h1.x = __float2bfloat16(v.z); h1.y = __float2bfloat16(v.w);
        l0.x = __float2bfloat16(v.x - __bfloat162float(h0.x));
        l0.y = __float2bfloat16(v.y - __bfloat162float(h0.y));
        l1.x = __float2bfloat16(v.z - __bfloat162float(h1.x));
        l1.y = __float2bfloat16(v.w - __bfloat162float(h1.y));
        *(__nv_bfloat162*)(g_xhi + i * 4)     = h0;
        *(__nv_bfloat162*)(g_xhi + i * 4 + 2) = h1;
        *(__nv_bfloat162*)(g_xlo + i * 4)     = l0;
        *(__nv_bfloat162*)(g_xlo + i * 4 + 2) = l1;
    }
    for (int i = id; i < NHEADS * NFEAT * NHID / 4; i += stride) {
        float4 v = ((const float4*)Wv)[i];
        int e = i * 4;
        int h = e >> 15;
        int r = e & 32767;
        int f = r >> 6, d = r & 63;
        int dst = f * HD + h * 64 + d;
        __nv_bfloat162 h0, h1, l0, l1;
        h0.x = __float2bfloat16(v.x); h0.y = __float2bfloat16(v.y);
        h1.x = __float2bfloat16(v.z); h1.y = __float2bfloat16(v.w);
        l0.x = __float2bfloat16(v.x - __bfloat162float(h0.x));
        l0.y = __float2bfloat16(v.y - __bfloat162float(h0.y));
        l1.x = __float2bfloat16(v.z - __bfloat162float(h1.x));
        l1.y = __float2bfloat16(v.w - __bfloat162float(h1.y));
        *(__nv_bfloat162*)(g_wthi + dst)     = h0;
        *(__nv_bfloat162*)(g_wthi + dst + 2) = h1;
        *(__nv_bfloat162*)(g_wtlo + dst)     = l0;
        *(__nv_bfloat162*)(g_wtlo + dst + 2) = l1;
    }
}

/* ------------------------------------------------------------------ */
/* gemm_csr: blocks 0..127 -> GEMM tile M=128 x N=128 (2 heads),       */
/*   double-buffered smem, reg prefetch, 1 barrier/iter, s1s2 fused.   */
/* blocks 128..639 -> CSR build.                                       */
#define A_LDM  24
#define B_LDM  136
#define AHB    (128*A_LDM*2)              /* 6144 B per A buffer  */
#define BHB    (16*B_LDM*2)               /* 4352 B per B buffer  */
#define OFF_AH 0
#define OFF_AL AHB
#define OFF_BH (2*AHB)
#define OFF_BL (2*AHB+BHB)
#define STAGE  (2*AHB+2*BHB)              /* 20992 B */

__global__ void __launch_bounds__(256)
gemm_csr(const float* __restrict__ adj, const float* __restrict__ a_heads) {
    const int bid = blockIdx.x, t = threadIdx.x;
    const int wid = t >> 5, lane = t & 31;

    if (bid >= 128) {
        /* ---- CSR build: warp per row ---- */
        const int row = (bid - 128) * 8 + wid;
        const float4* arow = (const float4*)(adj + (size_t)row * NN);
        const unsigned lt = (1u << lane) - 1u;
        int base = 0;
        for (int j0 = 0; j0 < NN / 4; j0 += 32) {
            float4 v = arow[j0 + lane];
            unsigned m0 = __ballot_sync(0xffffffffu, v.x > 0.0f);
            unsigned m1 = __ballot_sync(0xffffffffu, v.y > 0.0f);
            unsigned m2 = __ballot_sync(0xffffffffu, v.z > 0.0f);
            unsigned m3 = __ballot_sync(0xffffffffu, v.w > 0.0f);
            int below = __popc(m0 & lt) + __popc(m1 & lt) + __popc(m2 & lt) + __popc(m3 & lt);
            int jb = (j0 + lane) * 4;
            int p  = base + below;
            if (v.x > 0.0f) { if (p < MAXD) g_nbr[row * MAXD + p] = jb + 0; p++; }
            if (v.y > 0.0f) { if (p < MAXD) g_nbr[row * MAXD + p] = jb + 1; p++; }
            if (v.z > 0.0f) { if (p < MAXD) g_nbr[row * MAXD + p] = jb + 2; p++; }
            if (v.w > 0.0f) { if (p < MAXD) g_nbr[row * MAXD + p] = jb + 3; p++; }
            base += __popc(m0) + __popc(m1) + __popc(m2) + __popc(m3);
        }
        if (lane == 0) g_deg[row] = base < MAXD ? base : MAXD;
        return;
    }

    /* ---- GEMM ---- */
    __shared__ __align__(16) char raw[2 * STAGE];   /* 41984 B, Cs reuses */
    __shared__ float s_a12[256];

    const int hp = bid & 3;              /* head pair 0..3            */
    const int bm = (bid >> 2) * 128;     /* 32 m-tiles                */
    const int n0 = hp * 128;
    if (t < 256) s_a12[t] = a_heads[hp * 256 + t];

    const int wm = wid & 3;              /* 4 m-slices of 32          */
    const int wn = wid >> 2;             /* 2 n-slices of 64          */

    wmma::fragment<wmma::matrix_a, 16, 16, 16, __nv_bfloat16, wmma::row_major> ah[2], al[2];
    wmma::fragment<wmma::matrix_b, 16, 16, 16, __nv_bfloat16, wmma::row_major> bh[4], bl[4];
    wmma::fragment<wmma::accumulator, 16, 16, 16, float> acc[2][4];
#pragma unroll
    for (int i = 0; i < 2; i++)
#pragma unroll
        for (int j = 0; j < 4; j++) wmma::fill_fragment(acc[i][j], 0.0f);

    /* load coords: A 128x16 (2 uint4-segments/row), B 16x128 */
    const int ar = t >> 1, ac = (t & 1) * 8;
    const int br = t >> 4, bc = (t & 15) * 8;

    uint4 rah, ral, rbh, rbl;
    /* prime stage 0 */
    {
        rah = *(const uint4*)(g_xhi  + (size_t)(bm + ar) * NFEAT + ac);
        ral = *(const uint4*)(g_xlo  + (size_t)(bm + ar) * NFEAT + ac);
        rbh = *(const uint4*)(g_wthi + (size_t)br * HD + n0 + bc);
        rbl = *(const uint4*)(g_wtlo + (size_t)br * HD + n0 + bc);
        *(uint4*)(raw + OFF_AH + (ar * A_LDM + ac) * 2) = rah;
        *(uint4*)(raw + OFF_AL + (ar * A_LDM + ac) * 2) = ral;
        *(uint4*)(raw + OFF_BH + (br * B_LDM + bc) * 2) = rbh;
        *(uint4*)(raw + OFF_BL + (br * B_LDM + bc) * 2) = rbl;
    }
    __syncthreads();

    for (int ks = 0; ks < 32; ks++) {
        const char* st = raw + (ks & 1) * STAGE;
        const bool have = (ks + 1 < 32);
        if (have) {
            const int kt = (ks + 1) * 16;
            rah = *(const uint4*)(g_xhi  + (size_t)(bm + ar) * NFEAT + kt + ac);
            ral = *(const uint4*)(g_xlo  + (size_t)(bm + ar) * NFEAT + kt + ac);
            rbh = *(const uint4*)(g_wthi + (size_t)(kt + br) * HD + n0 + bc);
            rbl = *(const uint4*)(g_wtlo + (size_t)(kt + br) * HD + n0 + bc);
        }
        {
            const __nv_bfloat16* Ahi = (const __nv_bfloat16*)(st + OFF_AH);
            const __nv_bfloat16* Alo = (const __nv_bfloat16*)(st + OFF_AL);
            const __nv_bfloat16* Bhi = (const __nv_bfloat16*)(st + OFF_BH);
            const __nv_bfloat16* Blo = (const __nv_bfloat16*)(st + OFF_BL);
#pragma unroll
            for (int i = 0; i < 2; i++) {
                wmma::load_matrix_sync(ah[i], Ahi + (wm * 32 + i * 16) * A_LDM, A_LDM);
                wmma::load_matrix_sync(al[i], Alo + (wm * 32 + i * 16) * A_LDM, A_LDM);
            }
#pragma unroll
            for (int j = 0; j < 4; j++) {
                wmma::load_matrix_sync(bh[j], Bhi + wn * 64 + j * 16, B_LDM);
                wmma::load_matrix_sync(bl[j], Blo + wn * 64 + j * 16, B_LDM);
            }
#pragma unroll
            for (int i = 0; i < 2; i++)
#pragma unroll
                for (int j = 0; j < 4; j++) {
                    wmma::mma_sync(acc[i][j], ah[i], bh[j], acc[i][j]);
                    wmma::mma_sync(acc[i][j], ah[i], bl[j], acc[i][j]);
                    wmma::mma_sync(acc[i][j], al[i], bh[j], acc[i][j]);
                }
        }
        if (have) {
            char* nx = raw + ((ks + 1) & 1) * STAGE;
            *(uint4*)(nx + OFF_AH + (ar * A_LDM + ac) * 2) = rah;
            *(uint4*)(nx + OFF_AL + (ar * A_LDM + ac) * 2) = ral;
            *(uint4*)(nx + OFF_BH + (br * B_LDM + bc) * 2) = rbh;
            *(uint4*)(nx + OFF_BL + (br * B_LDM + bc) * 2) = rbl;
        }
        __syncthreads();
    }

    /* epilogue: two heads, one at a time through smem staging */
    float* Cs = (float*)raw;             /* 128 x 68 */
#pragma unroll
    for (int hh = 0; hh < 2; hh++) {
        if (wn == hh)
#pragma unroll
            for (int i = 0; i < 2; i++)
#pragma unroll
                for (int j = 0; j < 4; j++)
                    wmma::store_matrix_sync(Cs + (wm * 32 + i * 16) * 68 + j * 16,
                                            acc[i][j], 68, wmma::mem_row_major);
        __syncthreads();
        const int h = hp * 2 + hh;
        if (t < 128) {
            float s1 = 0.0f, s2 = 0.0f;
            const float* row = Cs + t * 68;
#pragma unroll 16
            for (int c = 0; c < 64; c++) {
                float f = row[c];
                s1 += f * s_a12[hh * 128 + c];
                s2 += f * s_a12[hh * 128 + 64 + c];
            }
            g_s1[h * NN + bm + t] = s1;
            g_s2[h * NN + bm + t] = s2;
        }
        for (int idx = t; idx < 128 * 64; idx += 256) {
            int rr = idx >> 6, cc = idx & 63;
            g_Wh[(size_t)(bm + rr) * HD + h * NHID + cc] = Cs[rr * 68 + cc];
        }
        __syncthreads();
    }
}

/* ------------------------------------------------------------------ */
/* layer-1 attention: block per node, warp per head, float2 gathers    */
__global__ void attn1(void) {
    const int i = blockIdx.x, t = threadIdx.x;
    const int h = t >> 5, lane = t & 31;
    __shared__ int   nb[MAXD];
    __shared__ float ew[NHEADS][MAXD];

    const int deg = g_deg[i];
    if (t < deg) nb[t] = g_nbr[i * MAXD + t];
    __syncthreads();

    const float s1i = g_s1[h * NN + i];
    float ev[8];
    float m = -1e30f;
#pragma unroll
    for (int c = 0; c < 8; c++) {
        int k = c * 32 + lane;
        float e = -1e30f;
        if (k < deg) {
            e = s1i + g_s2[h * NN + nb[k]];
            e = e > 0.0f ? e : ALPHA * e;
        }
        ev[c] = e; m = fmaxf(m, e);
    }
#pragma unroll
    for (int o = 16; o; o >>= 1) m = fmaxf(m, __shfl_xor_sync(0xffffffffu, m, o));
    float s = 0.0f;
#pragma unroll
    for (int c = 0; c < 8; c++) {
        int k = c * 32 + lane;
        if (k < deg) { float x = __expf(ev[c] - m); ew[h][k] = x; s += x; }
    }
#pragma unroll
    for (int o = 16; o; o >>= 1) s += __shfl_xor_sync(0xffffffffu, s, o);
    const float inv = 1.0f / s;
    __syncwarp();

    /* aggregation: lane owns columns 2*lane, 2*lane+1 (float2) */
    const int hoff = h * NHID;
    float2 a = {0, 0}, b = {0, 0}, c2 = {0, 0}, d = {0, 0};
    int k = 0;
    for (; k + 4 <= deg; k += 4) {
        float w0 = ew[h][k], w1 = ew[h][k + 1], w2 = ew[h][k + 2], w3 = ew[h][k + 3];
        float2 r0 = ((const float2*)(g_Wh + (size_t)nb[k]     * HD + hoff))[lane];
        float2 r1 = ((const float2*)(g_Wh + (size_t)nb[k + 1] * HD + hoff))[lane];
        float2 r2 = ((const float2*)(g_Wh + (size_t)nb[k + 2] * HD + hoff))[lane];
        float2 r3 = ((const float2*)(g_Wh + (size_t)nb[k + 3] * HD + hoff))[lane];
        a.x += w0 * r0.x; a.y += w0 * r0.y;
        b.x += w1 * r1.x; b.y += w1 * r1.y;
        c2.x += w2 * r2.x; c2.y += w2 * r2.y;
        d.x += w3 * r3.x; d.y += w3 * r3.y;
    }
    for (; k < deg; k++) {
        float w0 = ew[h][k];
        float2 r0 = ((const float2*)(g_Wh + (size_t)nb[k] * HD + hoff))[lane];
        a.x += w0 * r0.x; a.y += w0 * r0.y;
    }
    float v0 = (a.x + b.x + c2.x + d.x) * inv;
    float v1 = (a.y + b.y + c2.y + d.y) * inv;
    v0 = v0 > 0.0f ? v0 : (__expf(v0) - 1.0f);
    v1 = v1 > 0.0f ? v1 : (__expf(v1) - 1.0f);
    float2 o2; o2.x = v0; o2.y = v1;
    ((float2*)(g_h + (size_t)i * HD + hoff))[lane] = o2;
}

/* ------------------------------------------------------------------ */
/* out_proj split-K: grid = 128 m-tiles x 8 k-slices                   */
__global__ void out_proj_k(const float* __restrict__ W_out) {
    __shared__ float As[32][33];
    __shared__ float Bs[32][48];
    const int mt = blockIdx.x >> 3, ks = blockIdx.x & 7;
    const int t  = threadIdx.x;
    const int bm = mt * 32;
    const int k0 = ks * (HD / KSPLIT);
    const int tx = t & 15, ty = t >> 4;
    float acc[2][3] = {};

    for (int kt = k0; kt < k0 + HD / KSPLIT; kt += 32) {
        {
            int r = t >> 3, c4 = (t & 7) * 4;
            float4 v = *(const float4*)(g_h + (size_t)(bm + r) * HD + kt + c4);
            As[c4][r] = v.x; As[c4 + 1][r] = v.y; As[c4 + 2][r] = v.z; As[c4 + 3][r] = v.w;
        }
        for (int i = t; i < 32 * 48; i += 256) {
            int kk = i / 48, c = i - kk * 48;
            Bs[kk][c] = (c < NCLASS) ? W_out[(size_t)(kt + kk) * NCLASS + c] : 0.0f;
        }
        __syncthreads();
#pragma unroll 8
        for (int k = 0; k < 32; k++) {
            float a0 = As[k][ty * 2], a1 = As[k][ty * 2 + 1];
            float b0 = Bs[k][tx * 3], b1 = Bs[k][tx * 3 + 1], b2 = Bs[k][tx * 3 + 2];
            acc[0][0] += a0 * b0; acc[0][1] += a0 * b1; acc[0][2] += a0 * b2;
            acc[1][0] += a1 * b0; acc[1][1] += a1 * b1; acc[1][2] += a1 * b2;
        }
        __syncthreads();
    }
    float* dst = g_part + ((size_t)ks * NN + bm) * 48;
#pragma unroll
    for (int i = 0; i < 2; i++)
#pragma unroll
        for (int j = 0; j < 3; j++)
            dst[(ty * 2 + i) * 48 + tx * 3 + j] = acc[i][j];
}

/* ------------------------------------------------------------------ */
/* reduce: warp per row — sum 8 partials, write Wh2, fused p1/p2       */
__global__ void reduce_k(const float* __restrict__ a_out) {
    const int w = threadIdx.x >> 5, lane = threadIdx.x & 31;
    const int row = blockIdx.x * 8 + w;
    float v1 = 0.0f, v2 = 0.0f;
    const int c1 = lane, c2 = lane + 32;
#pragma unroll
    for (int s = 0; s < KSPLIT; s++) {
        const float* p = g_part + ((size_t)s * NN + row) * 48;
        v1 += p[c1];
        if (c2 < NCLASS) v2 += p[c2];
    }
    float p1 = 0.0f, p2 = 0.0f;
    if (c1 < NCLASS) {
        g_Wh2[row * NCLASS + c1] = v1;
        p1 += v1 * a_out[c1];
        p2 += v1 * a_out[NCLASS + c1];
    }
    if (c2 < NCLASS) {
        g_Wh2[row * NCLASS + c2] = v2;
        p1 += v2 * a_out[c2];
        p2 += v2 * a_out[NCLASS + c2];
    }
#pragma unroll
    for (int o = 16; o; o >>= 1) {
        p1 += __shfl_down_sync(0xffffffffu, p1, o);
        p2 += __shfl_down_sync(0xffffffffu, p2, o);
    }
    if (lane == 0) { g_p1[row] = p1; g_p2[row] = p2; }
}

/* ------------------------------------------------------------------ */
/* layer-2 attention: warp per node, no block barriers                 */
__global__ void attn2(float* __restrict__ out) {
    __shared__ float sw [8][MAXD];
    __shared__ int   snb[8][MAXD];
    const int w = threadIdx.x >> 5, lane = threadIdx.x & 31;
    const int i = blockIdx.x * 8 + w;
    const int deg = g_deg[i];

    const float p1i = g_p1[i];
    float ev[8];
    float m = -1e30f;
#pragma unroll
    for (int c = 0; c < 8; c++) {
        int k = c * 32 + lane;
        float e = -1e30f;
        if (k < deg) {
            int j = g_nbr[i * MAXD + k];
            snb[w][k] = j;
            e = p1i + g_p2[j];
            e = e > 0.0f ? e : ALPHA * e;
        }
        ev[c] = e; m = fmaxf(m, e);
    }
#pragma unroll
    for (int o = 16; o; o >>= 1) m = fmaxf(m, __shfl_xor_sync(0xffffffffu, m, o));
    float s = 0.0f;
#pragma unroll
    for (int c = 0; c < 8; c++) {
        int k = c * 32 + lane;
        if (k < deg) { float x = __expf(ev[c] - m); sw[w][k] = x; s += x; }
    }
#pragma unroll
    for (int o = 16; o; o >>= 1) s += __shfl_xor_sync(0xffffffffu, s, o);
    const float inv = 1.0f / s;
    __syncwarp();

    const int c1 = lane, c2 = lane + 32;
    float o1 = -1e30f, o2 = -1e30f;
    {
        float a0 = 0, a1 = 0, b0 = 0, b1 = 0;
        int k = 0;
        for (; k + 2 <= deg; k += 2) {
            float w0 = sw[w][k], w1 = sw[w][k + 1];
            const float* r0 = g_Wh2 + (size_t)snb[w][k]     * NCLASS;
            const float* r1 = g_Wh2 + (size_t)snb[w][k + 1] * NCLASS;
            if (c1 < NCLASS) { a0 += w0 * r0[c1]; b0 += w1 * r1[c1]; }
            if (c2 < NCLASS) { a1 += w0 * r0[c2]; b1 += w1 * r1[c2]; }
        }
        if (k < deg) {
            float w0 = sw[w][k];
            const float* r0 = g_Wh2 + (size_t)snb[w][k] * NCLASS;
            if (c1 < NCLASS) a0 += w0 * r0[c1];
            if (c2 < NCLASS) a1 += w0 * r0[c2];
        }
        if (c1 < NCLASS) {
            float v = (a0 + b0) * inv;
            o1 = v > 0.0f ? v : (__expf(v) - 1.0f);
        }
        if (c2 < NCLASS) {
            float v = (a1 + b1) * inv;
            o2 = v > 0.0f ? v : (__expf(v) - 1.0f);
        }
    }
    float mx = fmaxf(o1, o2);
#pragma unroll
    for (int o = 16; o; o >>= 1) mx = fmaxf(mx, __shfl_xor_sync(0xffffffffu, mx, o));
    float ex = ((c1 < NCLASS) ? __expf(o1 - mx) : 0.0f)
             + ((c2 < NCLASS) ? __expf(o2 - mx) : 0.0f);
#pragma unroll
    for (int o = 16; o; o >>= 1) ex += __shfl_xor_sync(0xffffffffu, ex, o);
    const float lse = mx + __logf(ex);
    if (c1 < NCLASS) out[i * NCLASS + c1] = o1 - lse;
    if (c2 < NCLASS) out[i * NCLASS + c2] = o2 - lse;
}

/* ------------------------------------------------------------------ */
extern "C" void kernel_launch(void* const* d_in, const int* in_sizes, int n_in,
                              void* d_out, int out_size) {
    const float *x = 0, *adj = 0, *W_heads = 0, *a_heads = 0, *W_out = 0, *a_out = 0;
    for (int i = 0; i < n_in; i++) {
        switch (in_sizes[i]) {
            case NN*NFEAT:            x       = (const float*)d_in[i]; break;
            case NN*NN:               adj     = (const float*)d_in[i]; break;
            case NHEADS*NFEAT*NHID:   W_heads = (const float*)d_in[i]; break;
            case NHEADS*2*NHID:       a_heads = (const float*)d_in[i]; break;
            case HD*NCLASS:           W_out   = (const float*)d_in[i]; break;
            case 2*NCLASS:            a_out   = (const float*)d_in[i]; break;
        }
    }
    float* out = (float*)d_out;

    convert   <<<256, 256>>>(x, W_heads);
    gemm_csr  <<<640, 256>>>(adj, a_heads);
    attn1     <<<NN, 256>>>();
    out_proj_k<<<1024, 256>>>(W_out);
    reduce_k  <<<NN / 8, 256>>>(a_out);
    attn2     <<<NN / 8, 256>>>(out);
}

// round 8
// speedup vs baseline: 1.0026x; 1.0026x over previous
#include <cuda_runtime.h>
#include <cuda_bf16.h>
#include <mma.h>
#include <math.h>
#include <stdint.h>

#define NN      4096
#define NFEAT   512
#define NHID    64
#define NHEADS  8
#define NCLASS  41
#define HD      (NHEADS*NHID)   /* 512 */
#define MAXD    256
#define ALPHA   0.2f
#define KSPLIT  4

using namespace nvcuda;

/* scratch */
__device__ int            g_deg[NN];
__device__ int            g_nbr[NN*MAXD];
__device__ float          g_Wh [NN*HD];
__device__ float          g_s1 [NHEADS*NN];
__device__ float          g_s2 [NHEADS*NN];
__device__ __nv_bfloat16  g_hhi[NN*HD];       /* layer-1 out, bf16 hi */
__device__ __nv_bfloat16  g_hlo[NN*HD];       /* layer-1 out, bf16 lo */
__device__ float          g_Wh2[NN*NCLASS];
__device__ float          g_p1 [NN];
__device__ float          g_p2 [NN];
__device__ float          g_part[KSPLIT*NN*48];

/* ------------------------------------------------------------------ */
/* fused1: blocks 0..511 -> bf16-split wmma GEMM (Wh = x @ W_head)     */
/*         + fused s1/s2 epilogue.                                     */
/* blocks 512..4607 -> CSR build, BLOCK per row (parallel latency).    */
__global__ void __launch_bounds__(256, 4)
fused1(const float* __restrict__ adj, const float* __restrict__ x,
       const float* __restrict__ Wv,  const float* __restrict__ a_heads) {
    const int bid = blockIdx.x, t = threadIdx.x;
    const int wid = t >> 5, lane = t & 31;

    if (bid >= 512) {
        /* ---- CSR build: one block per row, 4 passes of 256 float4 ---- */
        __shared__ int warp_cnt[8];
        __shared__ int s_base;
        const int row = bid - 512;
        const float4* arow = (const float4*)(adj + (size_t)row * NN);
        const unsigned lt = (1u << lane) - 1u;
        if (t == 0) s_base = 0;
        __syncthreads();
#pragma unroll
        for (int pass = 0; pass < 4; pass++) {
            float4 v = arow[pass * 256 + t];
            unsigned m0 = __ballot_sync(0xffffffffu, v.x > 0.0f);
            unsigned m1 = __ballot_sync(0xffffffffu, v.y > 0.0f);
            unsigned m2 = __ballot_sync(0xffffffffu, v.z > 0.0f);
            unsigned m3 = __ballot_sync(0xffffffffu, v.w > 0.0f);
            int below = __popc(m0 & lt) + __popc(m1 & lt) +
                        __popc(m2 & lt) + __popc(m3 & lt);
            int wtotal = __popc(m0) + __popc(m1) + __popc(m2) + __popc(m3);
            if (lane == 0) warp_cnt[wid] = wtotal;
            __syncthreads();
            int my_base = s_base + below;
#pragma unroll
            for (int w = 0; w < 8; w++) if (w < wid) my_base += warp_cnt[w];
            int jb = (pass * 256 + t) * 4;
            int p  = my_base;
            if (v.x > 0.0f) { if (p < MAXD) g_nbr[row * MAXD + p] = jb + 0; p++; }
            if (v.y > 0.0f) { if (p < MAXD) g_nbr[row * MAXD + p] = jb + 1; p++; }
            if (v.z > 0.0f) { if (p < MAXD) g_nbr[row * MAXD + p] = jb + 2; p++; }
            if (v.w > 0.0f) { if (p < MAXD) g_nbr[row * MAXD + p] = jb + 3; p++; }
            __syncthreads();
            if (t == 0) {
                int tot = 0;
#pragma unroll
                for (int w = 0; w < 8; w++) tot += warp_cnt[w];
                s_base += tot;
            }
            __syncthreads();
        }
        if (t == 0) g_deg[row] = s_base < MAXD ? s_base : MAXD;
        return;
    }

    /* ---- GEMM: block = 64 rows of x, one head; 8 warps 4x2 ---- */
    __shared__ __nv_bfloat16 As_hi[64 * 24];
    __shared__ __nv_bfloat16 As_lo[64 * 24];
    __shared__ __nv_bfloat16 Bs_hi[16 * 72];
    __shared__ __nv_bfloat16 Bs_lo[16 * 72];
    __shared__ float         Cs[64 * 72];
    __shared__ float         s_a12[128];

    const int bm = (bid & 63) * 64;
    const int h  = bid >> 6;
    const int wm = wid & 3;
    const int wn = wid >> 2;
    const float* Wb = Wv + (size_t)h * NFEAT * NHID;

    if (t < 128) s_a12[t] = a_heads[h * 128 + t];

    wmma::fragment<wmma::matrix_a, 16, 16, 16, __nv_bfloat16, wmma::row_major> ah, al;
    wmma::fragment<wmma::matrix_b, 16, 16, 16, __nv_bfloat16, wmma::row_major> bh, bl;
    wmma::fragment<wmma::accumulator, 16, 16, 16, float> acc[2];
    wmma::fill_fragment(acc[0], 0.0f);
    wmma::fill_fragment(acc[1], 0.0f);

    const int ar = t >> 2, ac = (t & 3) * 4;
    const int bk = t >> 4, bn = (t & 15) * 4;

    for (int kt = 0; kt < NFEAT; kt += 16) {
        float4 av = *(const float4*)(x + (size_t)(bm + ar) * NFEAT + kt + ac);
        float4 bv = *(const float4*)(Wb + (size_t)(kt + bk) * NHID + bn);
        {
            __nv_bfloat162 h0, h1, l0, l1;
            h0.x = __float2bfloat16(av.x); h0.y = __float2bfloat16(av.y);
            h1.x = __float2bfloat16(av.z); h1.y = __float2bfloat16(av.w);
            l0.x = __float2bfloat16(av.x - __bfloat162float(h0.x));
            l0.y = __float2bfloat16(av.y - __bfloat162float(h0.y));
            l1.x = __float2bfloat16(av.z - __bfloat162float(h1.x));
            l1.y = __float2bfloat16(av.w - __bfloat162float(h1.y));
            *(__nv_bfloat162*)(As_hi + ar * 24 + ac)     = h0;
            *(__nv_bfloat162*)(As_hi + ar * 24 + ac + 2) = h1;
            *(__nv_bfloat162*)(As_lo + ar * 24 + ac)     = l0;
            *(__nv_bfloat162*)(As_lo + ar * 24 + ac + 2) = l1;
        }
        {
            __nv_bfloat162 h0, h1, l0, l1;
            h0.x = __float2bfloat16(bv.x); h0.y = __float2bfloat16(bv.y);
            h1.x = __float2bfloat16(bv.z); h1.y = __float2bfloat16(bv.w);
            l0.x = __float2bfloat16(bv.x - __bfloat162float(h0.x));
            l0.y = __float2bfloat16(bv.y - __bfloat162float(h0.y));
            l1.x = __float2bfloat16(bv.z - __bfloat162float(h1.x));
            l1.y = __float2bfloat16(bv.w - __bfloat162float(h1.y));
            *(__nv_bfloat162*)(Bs_hi + bk * 72 + bn)     = h0;
            *(__nv_bfloat162*)(Bs_hi + bk * 72 + bn + 2) = h1;
            *(__nv_bfloat162*)(Bs_lo + bk * 72 + bn)     = l0;
            *(__nv_bfloat162*)(Bs_lo + bk * 72 + bn + 2) = l1;
        }
        __syncthreads();

        wmma::load_matrix_sync(ah, As_hi + wm * 16 * 24, 24);
        wmma::load_matrix_sync(al, As_lo + wm * 16 * 24, 24);
#pragma unroll
        for (int f = 0; f < 2; f++) {
            wmma::load_matrix_sync(bh, Bs_hi + wn * 32 + f * 16, 72);
            wmma::load_matrix_sync(bl, Bs_lo + wn * 32 + f * 16, 72);
            wmma::mma_sync(acc[f], ah, bh, acc[f]);
            wmma::mma_sync(acc[f], ah, bl, acc[f]);
            wmma::mma_sync(acc[f], al, bh, acc[f]);
        }
        __syncthreads();
    }

#pragma unroll
    for (int f = 0; f < 2; f++)
        wmma::store_matrix_sync(Cs + wm * 16 * 72 + wn * 32 + f * 16, acc[f],
                                72, wmma::mem_row_major);
    __syncthreads();

    if (t < 64) {
        float s1 = 0.0f, s2 = 0.0f;
        const float* row = Cs + t * 72;
#pragma unroll 16
        for (int c = 0; c < 64; c++) {
            float f = row[c];
            s1 += f * s_a12[c];
            s2 += f * s_a12[64 + c];
        }
        g_s1[h * NN + bm + t] = s1;
        g_s2[h * NN + bm + t] = s2;
    }
    for (int idx = t; idx < 64 * 64; idx += 256) {
        int rr = idx >> 6, cc = idx & 63;
        g_Wh[(size_t)(bm + rr) * HD + h * NHID + cc] = Cs[rr * 72 + cc];
    }
}

/* ------------------------------------------------------------------ */
/* layer-1 attention: block per node, warp per head; writes bf16 hi/lo */
__global__ void attn1(void) {
    const int i = blockIdx.x, t = threadIdx.x;
    const int h = t >> 5, lane = t & 31;
    __shared__ int   nb[MAXD];
    __shared__ float ew[NHEADS][MAXD];

    const int deg = g_deg[i];
    if (t < deg) nb[t] = g_nbr[i * MAXD + t];
    __syncthreads();

    const float s1i = g_s1[h * NN + i];
    float ev[8];
    float m = -1e30f;
#pragma unroll
    for (int c = 0; c < 8; c++) {
        int k = c * 32 + lane;
        float e = -1e30f;
        if (k < deg) {
            e = s1i + g_s2[h * NN + nb[k]];
            e = e > 0.0f ? e : ALPHA * e;
        }
        ev[c] = e; m = fmaxf(m, e);
    }
#pragma unroll
    for (int o = 16; o; o >>= 1) m = fmaxf(m, __shfl_xor_sync(0xffffffffu, m, o));
    float s = 0.0f;
#pragma unroll
    for (int c = 0; c < 8; c++) {
        int k = c * 32 + lane;
        if (k < deg) { float x = __expf(ev[c] - m); ew[h][k] = x; s += x; }
    }
#pragma unroll
    for (int o = 16; o; o >>= 1) s += __shfl_xor_sync(0xffffffffu, s, o);
    const float inv = 1.0f / s;
    __syncwarp();

    const int hoff = h * NHID;
    float a0 = 0, a1 = 0, b0 = 0, b1 = 0, c0 = 0, c1 = 0, d0 = 0, d1 = 0;
    int k = 0;
    for (; k + 4 <= deg; k += 4) {
        float w0 = ew[h][k], w1 = ew[h][k + 1], w2 = ew[h][k + 2], w3 = ew[h][k + 3];
        const float* r0 = g_Wh + (size_t)nb[k]     * HD + hoff;
        const float* r1 = g_Wh + (size_t)nb[k + 1] * HD + hoff;
        const float* r2 = g_Wh + (size_t)nb[k + 2] * HD + hoff;
        const float* r3 = g_Wh + (size_t)nb[k + 3] * HD + hoff;
        a0 += w0 * r0[lane]; a1 += w0 * r0[lane + 32];
        b0 += w1 * r1[lane]; b1 += w1 * r1[lane + 32];
        c0 += w2 * r2[lane]; c1 += w2 * r2[lane + 32];
        d0 += w3 * r3[lane]; d1 += w3 * r3[lane + 32];
    }
    for (; k < deg; k++) {
        float w0 = ew[h][k];
        const float* r0 = g_Wh + (size_t)nb[k] * HD + hoff;
        a0 += w0 * r0[lane]; a1 += w0 * r0[lane + 32];
    }
    float v0 = (a0 + b0 + c0 + d0) * inv;
    float v1 = (a1 + b1 + c1 + d1) * inv;
    v0 = v0 > 0.0f ? v0 : (__expf(v0) - 1.0f);
    v1 = v1 > 0.0f ? v1 : (__expf(v1) - 1.0f);
    /* emit bf16 hi/lo directly (consumed only by the wmma out_proj) */
    __nv_bfloat16 h0 = __float2bfloat16(v0);
    __nv_bfloat16 h1 = __float2bfloat16(v1);
    g_hhi[(size_t)i * HD + hoff + lane]      = h0;
    g_hhi[(size_t)i * HD + hoff + lane + 32] = h1;
    g_hlo[(size_t)i * HD + hoff + lane]      = __float2bfloat16(v0 - __bfloat162float(h0));
    g_hlo[(size_t)i * HD + hoff + lane + 32] = __float2bfloat16(v1 - __bfloat162float(h1));
}

/* ------------------------------------------------------------------ */
/* out_proj: bf16-split wmma GEMM Wh2 = h @ W_out                      */
/* grid = 64 m-tiles x 4 k-slices; BM=64, BN=64 (41 padded), BK=16     */
__global__ void __launch_bounds__(256)
out_proj_k(const float* __restrict__ W_out) {
    __shared__ __nv_bfloat16 As_hi[64 * 24];
    __shared__ __nv_bfloat16 As_lo[64 * 24];
    __shared__ __nv_bfloat16 Bs_hi[16 * 72];
    __shared__ __nv_bfloat16 Bs_lo[16 * 72];
    __shared__ float         Cs[64 * 72];

    const int mt = blockIdx.x >> 2, ks = blockIdx.x & 3;
    const int t  = threadIdx.x;
    const int wid = t >> 5;
    const int bm = mt * 64;
    const int k0 = ks * (HD / KSPLIT);   /* 128-wide K slice */
    const int wm = wid & 3, wn = wid >> 2;

    wmma::fragment<wmma::matrix_a, 16, 16, 16, __nv_bfloat16, wmma::row_major> ah, al;
    wmma::fragment<wmma::matrix_b, 16, 16, 16, __nv_bfloat16, wmma::row_major> bh, bl;
    wmma::fragment<wmma::accumulator, 16, 16, 16, float> acc[2];
    wmma::fill_fragment(acc[0], 0.0f);
    wmma::fill_fragment(acc[1], 0.0f);

    const int ar = t >> 2, ac = (t & 3) * 4;   /* A: 64x16 bf16, 8B/thread */

    for (int kt = k0; kt < k0 + HD / KSPLIT; kt += 16) {
        *(uint2*)(As_hi + ar * 24 + ac) = *(const uint2*)(g_hhi + (size_t)(bm + ar) * HD + kt + ac);
        *(uint2*)(As_lo + ar * 24 + ac) = *(const uint2*)(g_hlo + (size_t)(bm + ar) * HD + kt + ac);
        /* B: W_out[kt..kt+15][0..40] fp32 -> bf16 hi/lo, padded to 64 */
        for (int i = t; i < 16 * 64; i += 256) {
            int kk = i >> 6, c = i & 63;
            float v = (c < NCLASS) ? W_out[(size_t)(kt + kk) * NCLASS + c] : 0.0f;
            __nv_bfloat16 hi = __float2bfloat16(v);
            Bs_hi[kk * 72 + c] = hi;
            Bs_lo[kk * 72 + c] = __float2bfloat16(v - __bfloat162float(hi));
        }
        __syncthreads();
        wmma::load_matrix_sync(ah, As_hi + wm * 16 * 24, 24);
        wmma::load_matrix_sync(al, As_lo + wm * 16 * 24, 24);
#pragma unroll
        for (int f = 0; f < 2; f++) {
            wmma::load_matrix_sync(bh, Bs_hi + wn * 32 + f * 16, 72);
            wmma::load_matrix_sync(bl, Bs_lo + wn * 32 + f * 16, 72);
            wmma::mma_sync(acc[f], ah, bh, acc[f]);
            wmma::mma_sync(acc[f], ah, bl, acc[f]);
            wmma::mma_sync(acc[f], al, bh, acc[f]);
        }
        __syncthreads();
    }
#pragma unroll
    for (int f = 0; f < 2; f++)
        wmma::store_matrix_sync(Cs + wm * 16 * 72 + wn * 32 + f * 16, acc[f],
                                72, wmma::mem_row_major);
    __syncthreads();
    for (int idx = t; idx < 64 * 48; idx += 256) {
        int r = idx / 48, c = idx - r * 48;
        g_part[((size_t)ks * NN + bm + r) * 48 + c] = Cs[r * 72 + c];
    }
}

/* ------------------------------------------------------------------ */
/* reduce: warp per row — sum 4 partials, write Wh2, fused p1/p2       */
__global__ void reduce_k(const float* __restrict__ a_out) {
    const int w = threadIdx.x >> 5, lane = threadIdx.x & 31;
    const int row = blockIdx.x * 8 + w;
    float v1 = 0.0f, v2 = 0.0f;
    const int c1 = lane, c2 = lane + 32;
#pragma unroll
    for (int s = 0; s < KSPLIT; s++) {
        const float* p = g_part + ((size_t)s * NN + row) * 48;
        v1 += p[c1];
        if (c2 < NCLASS) v2 += p[c2];
    }
    float p1 = 0.0f, p2 = 0.0f;
    if (c1 < NCLASS) {
        g_Wh2[row * NCLASS + c1] = v1;
        p1 += v1 * a_out[c1];
        p2 += v1 * a_out[NCLASS + c1];
    }
    if (c2 < NCLASS) {
        g_Wh2[row * NCLASS + c2] = v2;
        p1 += v2 * a_out[c2];
        p2 += v2 * a_out[NCLASS + c2];
    }
#pragma unroll
    for (int o = 16; o; o >>= 1) {
        p1 += __shfl_down_sync(0xffffffffu, p1, o);
        p2 += __shfl_down_sync(0xffffffffu, p2, o);
    }
    if (lane == 0) { g_p1[row] = p1; g_p2[row] = p2; }
}

/* ------------------------------------------------------------------ */
/* layer-2 attention: warp per node, no block barriers                 */
__global__ void attn2(float* __restrict__ out) {
    __shared__ float sw [8][MAXD];
    __shared__ int   snb[8][MAXD];
    const int w = threadIdx.x >> 5, lane = threadIdx.x & 31;
    const int i = blockIdx.x * 8 + w;
    const int deg = g_deg[i];

    const float p1i = g_p1[i];
    float ev[8];
    float m = -1e30f;
#pragma unroll
    for (int c = 0; c < 8; c++) {
        int k = c * 32 + lane;
        float e = -1e30f;
        if (k < deg) {
            int j = g_nbr[i * MAXD + k];
            snb[w][k] = j;
            e = p1i + g_p2[j];
            e = e > 0.0f ? e : ALPHA * e;
        }
        ev[c] = e; m = fmaxf(m, e);
    }
#pragma unroll
    for (int o = 16; o; o >>= 1) m = fmaxf(m, __shfl_xor_sync(0xffffffffu, m, o));
    float s = 0.0f;
#pragma unroll
    for (int c = 0; c < 8; c++) {
        int k = c * 32 + lane;
        if (k < deg) { float x = __expf(ev[c] - m); sw[w][k] = x; s += x; }
    }
#pragma unroll
    for (int o = 16; o; o >>= 1) s += __shfl_xor_sync(0xffffffffu, s, o);
    const float inv = 1.0f / s;
    __syncwarp();

    const int c1 = lane, c2 = lane + 32;
    float o1 = -1e30f, o2 = -1e30f;
    {
        float a0 = 0, a1 = 0, b0 = 0, b1 = 0;
        int k = 0;
        for (; k + 2 <= deg; k += 2) {
            float w0 = sw[w][k], w1 = sw[w][k + 1];
            const float* r0 = g_Wh2 + (size_t)snb[w][k]     * NCLASS;
            const float* r1 = g_Wh2 + (size_t)snb[w][k + 1] * NCLASS;
            if (c1 < NCLASS) { a0 += w0 * r0[c1]; b0 += w1 * r1[c1]; }
            if (c2 < NCLASS) { a1 += w0 * r0[c2]; b1 += w1 * r1[c2]; }
        }
        if (k < deg) {
            float w0 = sw[w][k];
            const float* r0 = g_Wh2 + (size_t)snb[w][k] * NCLASS;
            if (c1 < NCLASS) a0 += w0 * r0[c1];
            if (c2 < NCLASS) a1 += w0 * r0[c2];
        }
        if (c1 < NCLASS) {
            float v = (a0 + b0) * inv;
            o1 = v > 0.0f ? v : (__expf(v) - 1.0f);
        }
        if (c2 < NCLASS) {
            float v = (a1 + b1) * inv;
            o2 = v > 0.0f ? v : (__expf(v) - 1.0f);
        }
    }
    float mx = fmaxf(o1, o2);
#pragma unroll
    for (int o = 16; o; o >>= 1) mx = fmaxf(mx, __shfl_xor_sync(0xffffffffu, mx, o));
    float ex = ((c1 < NCLASS) ? __expf(o1 - mx) : 0.0f)
             + ((c2 < NCLASS) ? __expf(o2 - mx) : 0.0f);
#pragma unroll
    for (int o = 16; o; o >>= 1) ex += __shfl_xor_sync(0xffffffffu, ex, o);
    const float lse = mx + __logf(ex);
    if (c1 < NCLASS) out[i * NCLASS + c1] = o1 - lse;
    if (c2 < NCLASS) out[i * NCLASS + c2] = o2 - lse;
}

/* ------------------------------------------------------------------ */
extern "C" void kernel_launch(void* const* d_in, const int* in_sizes, int n_in,
                              void* d_out, int out_size) {
    const float *x = 0, *adj = 0, *W_heads = 0, *a_heads = 0, *W_out = 0, *a_out = 0;
    for (int i = 0; i < n_in; i++) {
        switch (in_sizes[i]) {
            case NN*NFEAT:            x       = (const float*)d_in[i]; break;
            case NN*NN:               adj     = (const float*)d_in[i]; break;
            case NHEADS*NFEAT*NHID:   W_heads = (const float*)d_in[i]; break;
            case NHEADS*2*NHID:       a_heads = (const float*)d_in[i]; break;
            case HD*NCLASS:           W_out   = (const float*)d_in[i]; break;
            case 2*NCLASS:            a_out   = (const float*)d_in[i]; break;
        }
    }
    float* out = (float*)d_out;

    fused1    <<<512 + NN, 256>>>(adj, x, W_heads, a_heads);
    attn1     <<<NN, 256>>>();
    out_proj_k<<<256, 256>>>(W_out);
    reduce_k  <<<NN / 8, 256>>>(a_out);
    attn2     <<<NN / 8, 256>>>(out);
}

// round 9
// speedup vs baseline: 1.1009x; 1.0981x over previous
#include <cuda_runtime.h>
#include <cuda_bf16.h>
#include <mma.h>
#include <math.h>
#include <stdint.h>

#define NN      4096
#define NFEAT   512
#define NHID    64
#define NHEADS  8
#define NCLASS  41
#define HD      (NHEADS*NHID)   /* 512 */
#define MAXD    256
#define ALPHA   0.2f
#define KSPLIT  8

using namespace nvcuda;

/* scratch */
__device__ int   g_deg[NN];
__device__ int   g_nbr[NN*MAXD];
__device__ float g_Wh [NN*HD];
__device__ float g_s1 [NHEADS*NN];
__device__ float g_s2 [NHEADS*NN];
__device__ float g_h  [NN*HD];
__device__ float g_Wh2[NN*NCLASS];
__device__ float g_p1 [NN];
__device__ float g_p2 [NN];
__device__ float g_part[KSPLIT*NN*48];

/* ------------------------------------------------------------------ */
/* fused1: blocks 0..511 -> bf16-split wmma GEMM (Wh = x @ W_head)     */
/*         + fused s1/s2 epilogue. blocks 512..1023 -> CSR build.      */
__global__ void __launch_bounds__(256, 4)
fused1(const float* __restrict__ adj, const float* __restrict__ x,
       const float* __restrict__ Wv,  const float* __restrict__ a_heads) {
    const int bid = blockIdx.x, t = threadIdx.x;
    const int wid = t >> 5, lane = t & 31;

    if (bid >= 512) {
        /* ---- CSR build: warp per row ---- */
        const int row = (bid - 512) * 8 + wid;
        const float4* arow = (const float4*)(adj + (size_t)row * NN);
        const unsigned lt = (1u << lane) - 1u;
        int base = 0;
        for (int j0 = 0; j0 < NN / 4; j0 += 32) {
            float4 v = arow[j0 + lane];
            unsigned m0 = __ballot_sync(0xffffffffu, v.x > 0.0f);
            unsigned m1 = __ballot_sync(0xffffffffu, v.y > 0.0f);
            unsigned m2 = __ballot_sync(0xffffffffu, v.z > 0.0f);
            unsigned m3 = __ballot_sync(0xffffffffu, v.w > 0.0f);
            int below = __popc(m0 & lt) + __popc(m1 & lt) + __popc(m2 & lt) + __popc(m3 & lt);
            int jb = (j0 + lane) * 4;
            int p  = base + below;
            if (v.x > 0.0f) { if (p < MAXD) g_nbr[row * MAXD + p] = jb + 0; p++; }
            if (v.y > 0.0f) { if (p < MAXD) g_nbr[row * MAXD + p] = jb + 1; p++; }
            if (v.z > 0.0f) { if (p < MAXD) g_nbr[row * MAXD + p] = jb + 2; p++; }
            if (v.w > 0.0f) { if (p < MAXD) g_nbr[row * MAXD + p] = jb + 3; p++; }
            base += __popc(m0) + __popc(m1) + __popc(m2) + __popc(m3);
        }
        if (lane == 0) g_deg[row] = base < MAXD ? base : MAXD;
        return;
    }

    /* ---- GEMM: block = 64 rows of x, one head; 8 warps 4x2 ---- */
    __shared__ __nv_bfloat16 As_hi[64 * 24];
    __shared__ __nv_bfloat16 As_lo[64 * 24];
    __shared__ __nv_bfloat16 Bs_hi[16 * 72];
    __shared__ __nv_bfloat16 Bs_lo[16 * 72];
    __shared__ float         Cs[64 * 72];
    __shared__ float         s_a12[128];

    const int bm = (bid & 63) * 64;
    const int h  = bid >> 6;
    const int wm = wid & 3;
    const int wn = wid >> 2;
    const float* Wb = Wv + (size_t)h * NFEAT * NHID;

    if (t < 128) s_a12[t] = a_heads[h * 128 + t];

    wmma::fragment<wmma::matrix_a, 16, 16, 16, __nv_bfloat16, wmma::row_major> ah, al;
    wmma::fragment<wmma::matrix_b, 16, 16, 16, __nv_bfloat16, wmma::row_major> bh, bl;
    wmma::fragment<wmma::accumulator, 16, 16, 16, float> acc[2];
    wmma::fill_fragment(acc[0], 0.0f);
    wmma::fill_fragment(acc[1], 0.0f);

    const int ar = t >> 2, ac = (t & 3) * 4;
    const int bk = t >> 4, bn = (t & 15) * 4;

    for (int kt = 0; kt < NFEAT; kt += 16) {
        float4 av = *(const float4*)(x + (size_t)(bm + ar) * NFEAT + kt + ac);
        float4 bv = *(const float4*)(Wb + (size_t)(kt + bk) * NHID + bn);
        {
            __nv_bfloat162 h0, h1, l0, l1;
            h0.x = __float2bfloat16(av.x); h0.y = __float2bfloat16(av.y);
            h1.x = __float2bfloat16(av.z); h1.y = __float2bfloat16(av.w);
            l0.x = __float2bfloat16(av.x - __bfloat162float(h0.x));
            l0.y = __float2bfloat16(av.y - __bfloat162float(h0.y));
            l1.x = __float2bfloat16(av.z - __bfloat162float(h1.x));
            l1.y = __float2bfloat16(av.w - __bfloat162float(h1.y));
            *(__nv_bfloat162*)(As_hi + ar * 24 + ac)     = h0;
            *(__nv_bfloat162*)(As_hi + ar * 24 + ac + 2) = h1;
            *(__nv_bfloat162*)(As_lo + ar * 24 + ac)     = l0;
            *(__nv_bfloat162*)(As_lo + ar * 24 + ac + 2) = l1;
        }
        {
            __nv_bfloat162 h0, h1, l0, l1;
            h0.x = __float2bfloat16(bv.x); h0.y = __float2bfloat16(bv.y);
            h1.x = __float2bfloat16(bv.z); h1.y = __float2bfloat16(bv.w);
            l0.x = __float2bfloat16(bv.x - __bfloat162float(h0.x));
            l0.y = __float2bfloat16(bv.y - __bfloat162float(h0.y));
            l1.x = __float2bfloat16(bv.z - __bfloat162float(h1.x));
            l1.y = __float2bfloat16(bv.w - __bfloat162float(h1.y));
            *(__nv_bfloat162*)(Bs_hi + bk * 72 + bn)     = h0;
            *(__nv_bfloat162*)(Bs_hi + bk * 72 + bn + 2) = h1;
            *(__nv_bfloat162*)(Bs_lo + bk * 72 + bn)     = l0;
            *(__nv_bfloat162*)(Bs_lo + bk * 72 + bn + 2) = l1;
        }
        __syncthreads();

        wmma::load_matrix_sync(ah, As_hi + wm * 16 * 24, 24);
        wmma::load_matrix_sync(al, As_lo + wm * 16 * 24, 24);
#pragma unroll
        for (int f = 0; f < 2; f++) {
            wmma::load_matrix_sync(bh, Bs_hi + wn * 32 + f * 16, 72);
            wmma::load_matrix_sync(bl, Bs_lo + wn * 32 + f * 16, 72);
            wmma::mma_sync(acc[f], ah, bh, acc[f]);
            wmma::mma_sync(acc[f], ah, bl, acc[f]);
            wmma::mma_sync(acc[f], al, bh, acc[f]);
        }
        __syncthreads();
    }

#pragma unroll
    for (int f = 0; f < 2; f++)
        wmma::store_matrix_sync(Cs + wm * 16 * 72 + wn * 32 + f * 16, acc[f],
                                72, wmma::mem_row_major);
    __syncthreads();

    if (t < 64) {
        float s1 = 0.0f, s2 = 0.0f;
        const float* row = Cs + t * 72;
#pragma unroll 16
        for (int c = 0; c < 64; c++) {
            float f = row[c];
            s1 += f * s_a12[c];
            s2 += f * s_a12[64 + c];
        }
        g_s1[h * NN + bm + t] = s1;
        g_s2[h * NN + bm + t] = s2;
    }
    for (int idx = t; idx < 64 * 64; idx += 256) {
        int rr = idx >> 6, cc = idx & 63;
        g_Wh[(size_t)(bm + rr) * HD + h * NHID + cc] = Cs[rr * 72 + cc];
    }
}

/* ------------------------------------------------------------------ */
/* layer-1 attention: block per node, warp per head, shuffle softmax   */
__global__ void attn1(void) {
    const int i = blockIdx.x, t = threadIdx.x;
    const int h = t >> 5, lane = t & 31;
    __shared__ int   nb[MAXD];
    __shared__ float ew[NHEADS][MAXD];

    const int deg = g_deg[i];
    if (t < deg) nb[t] = g_nbr[i * MAXD + t];
    __syncthreads();

    const float s1i = g_s1[h * NN + i];
    float ev[8];
    float m = -1e30f;
#pragma unroll
    for (int c = 0; c < 8; c++) {
        int k = c * 32 + lane;
        float e = -1e30f;
        if (k < deg) {
            e = s1i + g_s2[h * NN + nb[k]];
            e = e > 0.0f ? e : ALPHA * e;
        }
        ev[c] = e; m = fmaxf(m, e);
    }
#pragma unroll
    for (int o = 16; o; o >>= 1) m = fmaxf(m, __shfl_xor_sync(0xffffffffu, m, o));
    float s = 0.0f;
#pragma unroll
    for (int c = 0; c < 8; c++) {
        int k = c * 32 + lane;
        if (k < deg) { float x = __expf(ev[c] - m); ew[h][k] = x; s += x; }
    }
#pragma unroll
    for (int o = 16; o; o >>= 1) s += __shfl_xor_sync(0xffffffffu, s, o);
    const float inv = 1.0f / s;
    __syncwarp();

    const int hoff = h * NHID;
    float a0 = 0, a1 = 0, b0 = 0, b1 = 0, c0 = 0, c1 = 0, d0 = 0, d1 = 0;
    int k = 0;
    for (; k + 4 <= deg; k += 4) {
        float w0 = ew[h][k], w1 = ew[h][k + 1], w2 = ew[h][k + 2], w3 = ew[h][k + 3];
        const float* r0 = g_Wh + (size_t)nb[k]     * HD + hoff;
        const float* r1 = g_Wh + (size_t)nb[k + 1] * HD + hoff;
        const float* r2 = g_Wh + (size_t)nb[k + 2] * HD + hoff;
        const float* r3 = g_Wh + (size_t)nb[k + 3] * HD + hoff;
        a0 += w0 * r0[lane]; a1 += w0 * r0[lane + 32];
        b0 += w1 * r1[lane]; b1 += w1 * r1[lane + 32];
        c0 += w2 * r2[lane]; c1 += w2 * r2[lane + 32];
        d0 += w3 * r3[lane]; d1 += w3 * r3[lane + 32];
    }
    for (; k < deg; k++) {
        float w0 = ew[h][k];
        const float* r0 = g_Wh + (size_t)nb[k] * HD + hoff;
        a0 += w0 * r0[lane]; a1 += w0 * r0[lane + 32];
    }
    float v0 = (a0 + b0 + c0 + d0) * inv;
    float v1 = (a1 + b1 + c1 + d1) * inv;
    v0 = v0 > 0.0f ? v0 : (__expf(v0) - 1.0f);
    v1 = v1 > 0.0f ? v1 : (__expf(v1) - 1.0f);
    g_h[(size_t)i * HD + hoff + lane]      = v0;
    g_h[(size_t)i * HD + hoff + lane + 32] = v1;
}

/* ------------------------------------------------------------------ */
/* out_proj split-K: grid = 64 m-tiles x 8 k-slices; BM=64, BK=32,     */
/* 4x3 per-thread register tile (12 FMA per 7 LDS)                     */
__global__ void out_proj_k(const float* __restrict__ W_out) {
    __shared__ float As[32][68];   /* [k][row 0..63], padded stride */
    __shared__ float Bs[32][48];
    const int mt = blockIdx.x >> 3, ks = blockIdx.x & 7;
    const int t  = threadIdx.x;
    const int bm = mt * 64;
    const int k0 = ks * (HD / KSPLIT);          /* 64-wide K slice */
    const int tx = t & 15, ty = t >> 4;
    float acc[4][3] = {};

    for (int kt = k0; kt < k0 + HD / KSPLIT; kt += 32) {
        {
            int r  = t >> 3, c4 = (t & 7) * 4;
            float4 v0 = *(const float4*)(g_h + (size_t)(bm + r)      * HD + kt + c4);
            float4 v1 = *(const float4*)(g_h + (size_t)(bm + 32 + r) * HD + kt + c4);
            As[c4 + 0][r] = v0.x; As[c4 + 1][r] = v0.y;
            As[c4 + 2][r] = v0.z; As[c4 + 3][r] = v0.w;
            As[c4 + 0][32 + r] = v1.x; As[c4 + 1][32 + r] = v1.y;
            As[c4 + 2][32 + r] = v1.z; As[c4 + 3][32 + r] = v1.w;
        }
        for (int i = t; i < 32 * 48; i += 256) {
            int kk = i / 48, c = i - kk * 48;
            Bs[kk][c] = (c < NCLASS) ? W_out[(size_t)(kt + kk) * NCLASS + c] : 0.0f;
        }
        __syncthreads();
#pragma unroll 8
        for (int k = 0; k < 32; k++) {
            float a0 = As[k][ty * 4], a1 = As[k][ty * 4 + 1];
            float a2 = As[k][ty * 4 + 2], a3 = As[k][ty * 4 + 3];
            float b0 = Bs[k][tx * 3], b1 = Bs[k][tx * 3 + 1], b2 = Bs[k][tx * 3 + 2];
            acc[0][0] += a0 * b0; acc[0][1] += a0 * b1; acc[0][2] += a0 * b2;
            acc[1][0] += a1 * b0; acc[1][1] += a1 * b1; acc[1][2] += a1 * b2;
            acc[2][0] += a2 * b0; acc[2][1] += a2 * b1; acc[2][2] += a2 * b2;
            acc[3][0] += a3 * b0; acc[3][1] += a3 * b1; acc[3][2] += a3 * b2;
        }
        __syncthreads();
    }
    float* dst = g_part + ((size_t)ks * NN + bm) * 48;
#pragma unroll
    for (int i = 0; i < 4; i++)
#pragma unroll
        for (int j = 0; j < 3; j++)
            dst[(ty * 4 + i) * 48 + tx * 3 + j] = acc[i][j];
}

/* ------------------------------------------------------------------ */
/* reduce: warp per row — sum 8 partials, write Wh2, fused p1/p2       */
__global__ void reduce_k(const float* __restrict__ a_out) {
    const int w = threadIdx.x >> 5, lane = threadIdx.x & 31;
    const int row = blockIdx.x * 8 + w;
    float v1 = 0.0f, v2 = 0.0f;
    const int c1 = lane, c2 = lane + 32;
#pragma unroll
    for (int s = 0; s < KSPLIT; s++) {
        const float* p = g_part + ((size_t)s * NN + row) * 48;
        v1 += p[c1];
        if (c2 < NCLASS) v2 += p[c2];
    }
    float p1 = 0.0f, p2 = 0.0f;
    if (c1 < NCLASS) {
        g_Wh2[row * NCLASS + c1] = v1;
        p1 += v1 * a_out[c1];
        p2 += v1 * a_out[NCLASS + c1];
    }
    if (c2 < NCLASS) {
        g_Wh2[row * NCLASS + c2] = v2;
        p1 += v2 * a_out[c2];
        p2 += v2 * a_out[NCLASS + c2];
    }
#pragma unroll
    for (int o = 16; o; o >>= 1) {
        p1 += __shfl_down_sync(0xffffffffu, p1, o);
        p2 += __shfl_down_sync(0xffffffffu, p2, o);
    }
    if (lane == 0) { g_p1[row] = p1; g_p2[row] = p2; }
}

/* ------------------------------------------------------------------ */
/* layer-2 attention: warp per node, no block barriers                 */
__global__ void attn2(float* __restrict__ out) {
    __shared__ float sw [8][MAXD];
    __shared__ int   snb[8][MAXD];
    const int w = threadIdx.x >> 5, lane = threadIdx.x & 31;
    const int i = blockIdx.x * 8 + w;
    const int deg = g_deg[i];

    const float p1i = g_p1[i];
    float ev[8];
    float m = -1e30f;
#pragma unroll
    for (int c = 0; c < 8; c++) {
        int k = c * 32 + lane;
        float e = -1e30f;
        if (k < deg) {
            int j = g_nbr[i * MAXD + k];
            snb[w][k] = j;
            e = p1i + g_p2[j];
            e = e > 0.0f ? e : ALPHA * e;
        }
        ev[c] = e; m = fmaxf(m, e);
    }
#pragma unroll
    for (int o = 16; o; o >>= 1) m = fmaxf(m, __shfl_xor_sync(0xffffffffu, m, o));
    float s = 0.0f;
#pragma unroll
    for (int c = 0; c < 8; c++) {
        int k = c * 32 + lane;
        if (k < deg) { float x = __expf(ev[c] - m); sw[w][k] = x; s += x; }
    }
#pragma unroll
    for (int o = 16; o; o >>= 1) s += __shfl_xor_sync(0xffffffffu, s, o);
    const float inv = 1.0f / s;
    __syncwarp();

    const int c1 = lane, c2 = lane + 32;
    float o1 = -1e30f, o2 = -1e30f;
    {
        float a0 = 0, a1 = 0, b0 = 0, b1 = 0;
        int k = 0;
        for (; k + 2 <= deg; k += 2) {
            float w0 = sw[w][k], w1 = sw[w][k + 1];
            const float* r0 = g_Wh2 + (size_t)snb[w][k]     * NCLASS;
            const float* r1 = g_Wh2 + (size_t)snb[w][k + 1] * NCLASS;
            if (c1 < NCLASS) { a0 += w0 * r0[c1]; b0 += w1 * r1[c1]; }
            if (c2 < NCLASS) { a1 += w0 * r0[c2]; b1 += w1 * r1[c2]; }
        }
        if (k < deg) {
            float w0 = sw[w][k];
            const float* r0 = g_Wh2 + (size_t)snb[w][k] * NCLASS;
            if (c1 < NCLASS) a0 += w0 * r0[c1];
            if (c2 < NCLASS) a1 += w0 * r0[c2];
        }
        if (c1 < NCLASS) {
            float v = (a0 + b0) * inv;
            o1 = v > 0.0f ? v : (__expf(v) - 1.0f);
        }
        if (c2 < NCLASS) {
            float v = (a1 + b1) * inv;
            o2 = v > 0.0f ? v : (__expf(v) - 1.0f);
        }
    }
    float mx = fmaxf(o1, o2);
#pragma unroll
    for (int o = 16; o; o >>= 1) mx = fmaxf(mx, __shfl_xor_sync(0xffffffffu, mx, o));
    float ex = ((c1 < NCLASS) ? __expf(o1 - mx) : 0.0f)
             + ((c2 < NCLASS) ? __expf(o2 - mx) : 0.0f);
#pragma unroll
    for (int o = 16; o; o >>= 1) ex += __shfl_xor_sync(0xffffffffu, ex, o);
    const float lse = mx + __logf(ex);
    if (c1 < NCLASS) out[i * NCLASS + c1] = o1 - lse;
    if (c2 < NCLASS) out[i * NCLASS + c2] = o2 - lse;
}

/* ------------------------------------------------------------------ */
extern "C" void kernel_launch(void* const* d_in, const int* in_sizes, int n_in,
                              void* d_out, int out_size) {
    const float *x = 0, *adj = 0, *W_heads = 0, *a_heads = 0, *W_out = 0, *a_out = 0;
    for (int i = 0; i < n_in; i++) {
        switch (in_sizes[i]) {
            case NN*NFEAT:            x       = (const float*)d_in[i]; break;
            case NN*NN:               adj     = (const float*)d_in[i]; break;
            case NHEADS*NFEAT*NHID:   W_heads = (const float*)d_in[i]; break;
            case NHEADS*2*NHID:       a_heads = (const float*)d_in[i]; break;
            case HD*NCLASS:           W_out   = (const float*)d_in[i]; break;
            case 2*NCLASS:            a_out   = (const float*)d_in[i]; break;
        }
    }
    float* out = (float*)d_out;

    fused1    <<<1024, 256>>>(adj, x, W_heads, a_heads);
    attn1     <<<NN, 256>>>();
    out_proj_k<<<512, 256>>>(W_out);
    reduce_k  <<<NN / 8, 256>>>(a_out);
    attn2     <<<NN / 8, 256>>>(out);
}

// round 10
// speedup vs baseline: 1.1097x; 1.0080x over previous
#include <cuda_runtime.h>
#include <cuda_bf16.h>
#include <mma.h>
#include <math.h>
#include <stdint.h>

#define NN      4096
#define NFEAT   512
#define NHID    64
#define NHEADS  8
#define NCLASS  41
#define HD      (NHEADS*NHID)   /* 512 */
#define MAXD    256
#define ALPHA   0.2f
#define KSPLIT  8

using namespace nvcuda;

/* scratch */
__device__ int   g_deg[NN];
__device__ int   g_nbr[NN*MAXD];
__device__ float g_Wh [NN*HD];
__device__ float g_s1 [NHEADS*NN];
__device__ float g_s2 [NHEADS*NN];
__device__ float g_h  [NN*HD];
__device__ float g_Wh2[NN*NCLASS];
__device__ float g_p1 [NN];
__device__ float g_p2 [NN];
__device__ float g_part[KSPLIT*NN*48];

/* ------------------------------------------------------------------ */
__device__ __forceinline__ void csr_chunk(float4 v, int jb, int row,
                                          int& base, unsigned lt) {
    unsigned m0 = __ballot_sync(0xffffffffu, v.x > 0.0f);
    unsigned m1 = __ballot_sync(0xffffffffu, v.y > 0.0f);
    unsigned m2 = __ballot_sync(0xffffffffu, v.z > 0.0f);
    unsigned m3 = __ballot_sync(0xffffffffu, v.w > 0.0f);
    int below = __popc(m0 & lt) + __popc(m1 & lt) +
                __popc(m2 & lt) + __popc(m3 & lt);
    int p = base + below;
    if (v.x > 0.0f) { if (p < MAXD) g_nbr[row * MAXD + p] = jb + 0; p++; }
    if (v.y > 0.0f) { if (p < MAXD) g_nbr[row * MAXD + p] = jb + 1; p++; }
    if (v.z > 0.0f) { if (p < MAXD) g_nbr[row * MAXD + p] = jb + 2; p++; }
    if (v.w > 0.0f) { if (p < MAXD) g_nbr[row * MAXD + p] = jb + 3; p++; }
    base += __popc(m0) + __popc(m1) + __popc(m2) + __popc(m3);
}

/* ------------------------------------------------------------------ */
/* fused1: blocks 0..511 -> bf16-split wmma GEMM (Wh = x @ W_head)     */
/*         + fused s1/s2 epilogue. blocks 512..1023 -> CSR build       */
/*         (warp per row, 4-way MLP-unrolled scan).                    */
__global__ void __launch_bounds__(256, 4)
fused1(const float* __restrict__ adj, const float* __restrict__ x,
       const float* __restrict__ Wv,  const float* __restrict__ a_heads) {
    const int bid = blockIdx.x, t = threadIdx.x;
    const int wid = t >> 5, lane = t & 31;

    if (bid >= 512) {
        /* ---- CSR build: warp per row, 4 independent loads per iter ---- */
        const int row = (bid - 512) * 8 + wid;
        const float4* arow = (const float4*)(adj + (size_t)row * NN);
        const unsigned lt = (1u << lane) - 1u;
        int base = 0;
#pragma unroll 2
        for (int j0 = 0; j0 < NN / 4; j0 += 128) {
            float4 v0 = arow[j0 +       lane];
            float4 v1 = arow[j0 +  32 + lane];
            float4 v2 = arow[j0 +  64 + lane];
            float4 v3 = arow[j0 +  96 + lane];
            csr_chunk(v0, (j0 +       lane) * 4, row, base, lt);
            csr_chunk(v1, (j0 +  32 + lane) * 4, row, base, lt);
            csr_chunk(v2, (j0 +  64 + lane) * 4, row, base, lt);
            csr_chunk(v3, (j0 +  96 + lane) * 4, row, base, lt);
        }
        if (lane == 0) g_deg[row] = base < MAXD ? base : MAXD;
        return;
    }

    /* ---- GEMM: block = 64 rows of x, one head; 8 warps 4x2 ---- */
    __shared__ __nv_bfloat16 As_hi[64 * 24];
    __shared__ __nv_bfloat16 As_lo[64 * 24];
    __shared__ __nv_bfloat16 Bs_hi[16 * 72];
    __shared__ __nv_bfloat16 Bs_lo[16 * 72];
    __shared__ float         Cs[64 * 72];
    __shared__ float         s_a12[128];

    const int bm = (bid & 63) * 64;
    const int h  = bid >> 6;
    const int wm = wid & 3;
    const int wn = wid >> 2;
    const float* Wb = Wv + (size_t)h * NFEAT * NHID;

    if (t < 128) s_a12[t] = a_heads[h * 128 + t];

    wmma::fragment<wmma::matrix_a, 16, 16, 16, __nv_bfloat16, wmma::row_major> ah, al;
    wmma::fragment<wmma::matrix_b, 16, 16, 16, __nv_bfloat16, wmma::row_major> bh, bl;
    wmma::fragment<wmma::accumulator, 16, 16, 16, float> acc[2];
    wmma::fill_fragment(acc[0], 0.0f);
    wmma::fill_fragment(acc[1], 0.0f);

    const int ar = t >> 2, ac = (t & 3) * 4;
    const int bk = t >> 4, bn = (t & 15) * 4;

    for (int kt = 0; kt < NFEAT; kt += 16) {
        float4 av = *(const float4*)(x + (size_t)(bm + ar) * NFEAT + kt + ac);
        float4 bv = *(const float4*)(Wb + (size_t)(kt + bk) * NHID + bn);
        {
            __nv_bfloat162 h0, h1, l0, l1;
            h0.x = __float2bfloat16(av.x); h0.y = __float2bfloat16(av.y);
            h1.x = __float2bfloat16(av.z); h1.y = __float2bfloat16(av.w);
            l0.x = __float2bfloat16(av.x - __bfloat162float(h0.x));
            l0.y = __float2bfloat16(av.y - __bfloat162float(h0.y));
            l1.x = __float2bfloat16(av.z - __bfloat162float(h1.x));
            l1.y = __float2bfloat16(av.w - __bfloat162float(h1.y));
            *(__nv_bfloat162*)(As_hi + ar * 24 + ac)     = h0;
            *(__nv_bfloat162*)(As_hi + ar * 24 + ac + 2) = h1;
            *(__nv_bfloat162*)(As_lo + ar * 24 + ac)     = l0;
            *(__nv_bfloat162*)(As_lo + ar * 24 + ac + 2) = l1;
        }
        {
            __nv_bfloat162 h0, h1, l0, l1;
            h0.x = __float2bfloat16(bv.x); h0.y = __float2bfloat16(bv.y);
            h1.x = __float2bfloat16(bv.z); h1.y = __float2bfloat16(bv.w);
            l0.x = __float2bfloat16(bv.x - __bfloat162float(h0.x));
            l0.y = __float2bfloat16(bv.y - __bfloat162float(h0.y));
            l1.x = __float2bfloat16(bv.z - __bfloat162float(h1.x));
            l1.y = __float2bfloat16(bv.w - __bfloat162float(h1.y));
            *(__nv_bfloat162*)(Bs_hi + bk * 72 + bn)     = h0;
            *(__nv_bfloat162*)(Bs_hi + bk * 72 + bn + 2) = h1;
            *(__nv_bfloat162*)(Bs_lo + bk * 72 + bn)     = l0;
            *(__nv_bfloat162*)(Bs_lo + bk * 72 + bn + 2) = l1;
        }
        __syncthreads();

        wmma::load_matrix_sync(ah, As_hi + wm * 16 * 24, 24);
        wmma::load_matrix_sync(al, As_lo + wm * 16 * 24, 24);
#pragma unroll
        for (int f = 0; f < 2; f++) {
            wmma::load_matrix_sync(bh, Bs_hi + wn * 32 + f * 16, 72);
            wmma::load_matrix_sync(bl, Bs_lo + wn * 32 + f * 16, 72);
            wmma::mma_sync(acc[f], ah, bh, acc[f]);
            wmma::mma_sync(acc[f], ah, bl, acc[f]);
            wmma::mma_sync(acc[f], al, bh, acc[f]);
        }
        __syncthreads();
    }

#pragma unroll
    for (int f = 0; f < 2; f++)
        wmma::store_matrix_sync(Cs + wm * 16 * 72 + wn * 32 + f * 16, acc[f],
                                72, wmma::mem_row_major);
    __syncthreads();

    if (t < 64) {
        float s1 = 0.0f, s2 = 0.0f;
        const float* row = Cs + t * 72;
#pragma unroll 16
        for (int c = 0; c < 64; c++) {
            float f = row[c];
            s1 += f * s_a12[c];
            s2 += f * s_a12[64 + c];
        }
        g_s1[h * NN + bm + t] = s1;
        g_s2[h * NN + bm + t] = s2;
    }
    for (int idx = t; idx < 64 * 64; idx += 256) {
        int rr = idx >> 6, cc = idx & 63;
        g_Wh[(size_t)(bm + rr) * HD + h * NHID + cc] = Cs[rr * 72 + cc];
    }
}

/* ------------------------------------------------------------------ */
/* layer-1 attention: block per node, warp per head, shuffle softmax   */
__global__ void attn1(void) {
    const int i = blockIdx.x, t = threadIdx.x;
    const int h = t >> 5, lane = t & 31;
    __shared__ int   nb[MAXD];
    __shared__ float ew[NHEADS][MAXD];

    const int deg = g_deg[i];
    if (t < deg) nb[t] = g_nbr[i * MAXD + t];
    __syncthreads();

    const float s1i = g_s1[h * NN + i];
    float ev[8];
    float m = -1e30f;
#pragma unroll
    for (int c = 0; c < 8; c++) {
        int k = c * 32 + lane;
        float e = -1e30f;
        if (k < deg) {
            e = s1i + g_s2[h * NN + nb[k]];
            e = e > 0.0f ? e : ALPHA * e;
        }
        ev[c] = e; m = fmaxf(m, e);
    }
#pragma unroll
    for (int o = 16; o; o >>= 1) m = fmaxf(m, __shfl_xor_sync(0xffffffffu, m, o));
    float s = 0.0f;
#pragma unroll
    for (int c = 0; c < 8; c++) {
        int k = c * 32 + lane;
        if (k < deg) { float x = __expf(ev[c] - m); ew[h][k] = x; s += x; }
    }
#pragma unroll
    for (int o = 16; o; o >>= 1) s += __shfl_xor_sync(0xffffffffu, s, o);
    const float inv = 1.0f / s;
    __syncwarp();

    const int hoff = h * NHID;
    float a0 = 0, a1 = 0, b0 = 0, b1 = 0, c0 = 0, c1 = 0, d0 = 0, d1 = 0;
    int k = 0;
    for (; k + 4 <= deg; k += 4) {
        float w0 = ew[h][k], w1 = ew[h][k + 1], w2 = ew[h][k + 2], w3 = ew[h][k + 3];
        const float* r0 = g_Wh + (size_t)nb[k]     * HD + hoff;
        const float* r1 = g_Wh + (size_t)nb[k + 1] * HD + hoff;
        const float* r2 = g_Wh + (size_t)nb[k + 2] * HD + hoff;
        const float* r3 = g_Wh + (size_t)nb[k + 3] * HD + hoff;
        a0 += w0 * r0[lane]; a1 += w0 * r0[lane + 32];
        b0 += w1 * r1[lane]; b1 += w1 * r1[lane + 32];
        c0 += w2 * r2[lane]; c1 += w2 * r2[lane + 32];
        d0 += w3 * r3[lane]; d1 += w3 * r3[lane + 32];
    }
    for (; k < deg; k++) {
        float w0 = ew[h][k];
        const float* r0 = g_Wh + (size_t)nb[k] * HD + hoff;
        a0 += w0 * r0[lane]; a1 += w0 * r0[lane + 32];
    }
    float v0 = (a0 + b0 + c0 + d0) * inv;
    float v1 = (a1 + b1 + c1 + d1) * inv;
    v0 = v0 > 0.0f ? v0 : (__expf(v0) - 1.0f);
    v1 = v1 > 0.0f ? v1 : (__expf(v1) - 1.0f);
    g_h[(size_t)i * HD + hoff + lane]      = v0;
    g_h[(size_t)i * HD + hoff + lane + 32] = v1;
}

/* ------------------------------------------------------------------ */
/* out_proj split-K: grid = 64 m-tiles x 8 k-slices; BM=64, BK=32,     */
/* 4x3 per-thread register tile                                        */
__global__ void out_proj_k(const float* __restrict__ W_out) {
    __shared__ float As[32][68];
    __shared__ float Bs[32][48];
    const int mt = blockIdx.x >> 3, ks = blockIdx.x & 7;
    const int t  = threadIdx.x;
    const int bm = mt * 64;
    const int k0 = ks * (HD / KSPLIT);
    const int tx = t & 15, ty = t >> 4;
    float acc[4][3] = {};

    for (int kt = k0; kt < k0 + HD / KSPLIT; kt += 32) {
        {
            int r  = t >> 3, c4 = (t & 7) * 4;
            float4 v0 = *(const float4*)(g_h + (size_t)(bm + r)      * HD + kt + c4);
            float4 v1 = *(const float4*)(g_h + (size_t)(bm + 32 + r) * HD + kt + c4);
            As[c4 + 0][r] = v0.x; As[c4 + 1][r] = v0.y;
            As[c4 + 2][r] = v0.z; As[c4 + 3][r] = v0.w;
            As[c4 + 0][32 + r] = v1.x; As[c4 + 1][32 + r] = v1.y;
            As[c4 + 2][32 + r] = v1.z; As[c4 + 3][32 + r] = v1.w;
        }
        for (int i = t; i < 32 * 48; i += 256) {
            int kk = i / 48, c = i - kk * 48;
            Bs[kk][c] = (c < NCLASS) ? W_out[(size_t)(kt + kk) * NCLASS + c] : 0.0f;
        }
        __syncthreads();
#pragma unroll 8
        for (int k = 0; k < 32; k++) {
            float a0 = As[k][ty * 4], a1 = As[k][ty * 4 + 1];
            float a2 = As[k][ty * 4 + 2], a3 = As[k][ty * 4 + 3];
            float b0 = Bs[k][tx * 3], b1 = Bs[k][tx * 3 + 1], b2 = Bs[k][tx * 3 + 2];
            acc[0][0] += a0 * b0; acc[0][1] += a0 * b1; acc[0][2] += a0 * b2;
            acc[1][0] += a1 * b0; acc[1][1] += a1 * b1; acc[1][2] += a1 * b2;
            acc[2][0] += a2 * b0; acc[2][1] += a2 * b1; acc[2][2] += a2 * b2;
            acc[3][0] += a3 * b0; acc[3][1] += a3 * b1; acc[3][2] += a3 * b2;
        }
        __syncthreads();
    }
    float* dst = g_part + ((size_t)ks * NN + bm) * 48;
#pragma unroll
    for (int i = 0; i < 4; i++)
#pragma unroll
        for (int j = 0; j < 3; j++)
            dst[(ty * 4 + i) * 48 + tx * 3 + j] = acc[i][j];
}

/* ------------------------------------------------------------------ */
/* reduce: warp per row — sum 8 partials, write Wh2, fused p1/p2       */
__global__ void reduce_k(const float* __restrict__ a_out) {
    const int w = threadIdx.x >> 5, lane = threadIdx.x & 31;
    const int row = blockIdx.x * 8 + w;
    float v1 = 0.0f, v2 = 0.0f;
    const int c1 = lane, c2 = lane + 32;
#pragma unroll
    for (int s = 0; s < KSPLIT; s++) {
        const float* p = g_part + ((size_t)s * NN + row) * 48;
        v1 += p[c1];
        if (c2 < NCLASS) v2 += p[c2];
    }
    float p1 = 0.0f, p2 = 0.0f;
    if (c1 < NCLASS) {
        g_Wh2[row * NCLASS + c1] = v1;
        p1 += v1 * a_out[c1];
        p2 += v1 * a_out[NCLASS + c1];
    }
    if (c2 < NCLASS) {
        g_Wh2[row * NCLASS + c2] = v2;
        p1 += v2 * a_out[c2];
        p2 += v2 * a_out[NCLASS + c2];
    }
#pragma unroll
    for (int o = 16; o; o >>= 1) {
        p1 += __shfl_down_sync(0xffffffffu, p1, o);
        p2 += __shfl_down_sync(0xffffffffu, p2, o);
    }
    if (lane == 0) { g_p1[row] = p1; g_p2[row] = p2; }
}

/* ------------------------------------------------------------------ */
/* layer-2 attention: warp per node, no block barriers                 */
__global__ void attn2(float* __restrict__ out) {
    __shared__ float sw [8][MAXD];
    __shared__ int   snb[8][MAXD];
    const int w = threadIdx.x >> 5, lane = threadIdx.x & 31;
    const int i = blockIdx.x * 8 + w;
    const int deg = g_deg[i];

    const float p1i = g_p1[i];
    float ev[8];
    float m = -1e30f;
#pragma unroll
    for (int c = 0; c < 8; c++) {
        int k = c * 32 + lane;
        float e = -1e30f;
        if (k < deg) {
            int j = g_nbr[i * MAXD + k];
            snb[w][k] = j;
            e = p1i + g_p2[j];
            e = e > 0.0f ? e : ALPHA * e;
        }
        ev[c] = e; m = fmaxf(m, e);
    }
#pragma unroll
    for (int o = 16; o; o >>= 1) m = fmaxf(m, __shfl_xor_sync(0xffffffffu, m, o));
    float s = 0.0f;
#pragma unroll
    for (int c = 0; c < 8; c++) {
        int k = c * 32 + lane;
        if (k < deg) { float x = __expf(ev[c] - m); sw[w][k] = x; s += x; }
    }
#pragma unroll
    for (int o = 16; o; o >>= 1) s += __shfl_xor_sync(0xffffffffu, s, o);
    const float inv = 1.0f / s;
    __syncwarp();

    const int c1 = lane, c2 = lane + 32;
    float o1 = -1e30f, o2 = -1e30f;
    {
        float a0 = 0, a1 = 0, b0 = 0, b1 = 0;
        int k = 0;
        for (; k + 2 <= deg; k += 2) {
            float w0 = sw[w][k], w1 = sw[w][k + 1];
            const float* r0 = g_Wh2 + (size_t)snb[w][k]     * NCLASS;
            const float* r1 = g_Wh2 + (size_t)snb[w][k + 1] * NCLASS;
            if (c1 < NCLASS) { a0 += w0 * r0[c1]; b0 += w1 * r1[c1]; }
            if (c2 < NCLASS) { a1 += w0 * r0[c2]; b1 += w1 * r1[c2]; }
        }
        if (k < deg) {
            float w0 = sw[w][k];
            const float* r0 = g_Wh2 + (size_t)snb[w][k] * NCLASS;
            if (c1 < NCLASS) a0 += w0 * r0[c1];
            if (c2 < NCLASS) a1 += w0 * r0[c2];
        }
        if (c1 < NCLASS) {
            float v = (a0 + b0) * inv;
            o1 = v > 0.0f ? v : (__expf(v) - 1.0f);
        }
        if (c2 < NCLASS) {
            float v = (a1 + b1) * inv;
            o2 = v > 0.0f ? v : (__expf(v) - 1.0f);
        }
    }
    float mx = fmaxf(o1, o2);
#pragma unroll
    for (int o = 16; o; o >>= 1) mx = fmaxf(mx, __shfl_xor_sync(0xffffffffu, mx, o));
    float ex = ((c1 < NCLASS) ? __expf(o1 - mx) : 0.0f)
             + ((c2 < NCLASS) ? __expf(o2 - mx) : 0.0f);
#pragma unroll
    for (int o = 16; o; o >>= 1) ex += __shfl_xor_sync(0xffffffffu, ex, o);
    const float lse = mx + __logf(ex);
    if (c1 < NCLASS) out[i * NCLASS + c1] = o1 - lse;
    if (c2 < NCLASS) out[i * NCLASS + c2] = o2 - lse;
}

/* ------------------------------------------------------------------ */
extern "C" void kernel_launch(void* const* d_in, const int* in_sizes, int n_in,
                              void* d_out, int out_size) {
    const float *x = 0, *adj = 0, *W_heads = 0, *a_heads = 0, *W_out = 0, *a_out = 0;
    for (int i = 0; i < n_in; i++) {
        switch (in_sizes[i]) {
            case NN*NFEAT:            x       = (const float*)d_in[i]; break;
            case NN*NN:               adj     = (const float*)d_in[i]; break;
            case NHEADS*NFEAT*NHID:   W_heads = (const float*)d_in[i]; break;
            case NHEADS*2*NHID:       a_heads = (const float*)d_in[i]; break;
            case HD*NCLASS:           W_out   = (const float*)d_in[i]; break;
            case 2*NCLASS:            a_out   = (const float*)d_in[i]; break;
        }
    }
    float* out = (float*)d_out;

    fused1    <<<1024, 256>>>(adj, x, W_heads, a_heads);
    attn1     <<<NN, 256>>>();
    out_proj_k<<<512, 256>>>(W_out);
    reduce_k  <<<NN / 8, 256>>>(a_out);
    attn2     <<<NN / 8, 256>>>(out);
}